// round 14
// baseline (speedup 1.0000x reference)
#include <cuda_runtime.h>
#include <cuda_fp16.h>
#include <cstdint>

#define NI 32            // i-tiles per CTA
#define GI 4             // grid.x (GI*NI = 128 = L)

// ---------------- device scratch (no allocs allowed) ----------------
// word order within a 64-word row: w = kt*8 + 2*tg + h  (kt=0..7, tg=0..3, h=0..1)
__device__ unsigned int g_Ah[4096*64];     // [r][64], r=i*32+b
__device__ unsigned int g_Bh[32*128*64];   // [b][j][64]
__device__ float        g_Vb[32*128*128];  // [b][j][c] fp32 value
__device__ uint2        g_W2h[128*32];     // [c][kt*4+tg] fp16 frag pairs

// ---------------- main smem layout (float units) ----------------
#define F_SA 0                 // 32 t * 72 words
#define F_SB 2304              // 128 j * 72 words
#define F_SW 11520             // 64 c * 72 words
#define F_SV 16128             // 128 j * 72 floats
#define F_SP 25344             // 2 bufs * (2 tt * 4 jq * 64) = 2048
#define F_BV 27392             // 64
#define SMEM_MAIN (27456*4)    // 109824 B -> 2 CTAs/SM

static __device__ __forceinline__ uint32_t pack_h2(float lo, float hi){
    uint32_t r;
    asm("cvt.rn.f16x2.f32 %0, %1, %2;" : "=r"(r) : "f"(hi), "f"(lo));
    return r;
}
static __device__ __forceinline__ uint32_t relu2add(uint32_t a, uint32_t b){
    uint32_t r;
    asm("{ .reg .b32 t; add.f16x2 t, %1, %2; max.f16x2 %0, t, %3; }"
        : "=r"(r) : "r"(a), "r"(b), "r"(0u));
    return r;
}

// ------------------------- prep GEMM inners -------------------------
static __device__ __forceinline__ void gemm_inner4(
    const float* __restrict__ sXr, const float* __restrict__ sW,
    float acc[4][8], int tx)
{
    #pragma unroll 2
    for (int k4 = 0; k4 < 128; k4 += 4){
        float ax[4][4];
        #pragma unroll
        for (int q = 0; q < 4; q++)
            *(float4*)ax[q] = *(const float4*)(sXr + q*128 + k4);
        #pragma unroll
        for (int kk = 0; kk < 4; kk++){
            float w[8];
            *(float4*)&w[0] = *(const float4*)(sW + (k4+kk)*128 + tx*8);
            *(float4*)&w[4] = *(const float4*)(sW + (k4+kk)*128 + tx*8 + 4);
            #pragma unroll
            for (int c = 0; c < 8; c++){
                acc[0][c] += ax[0][kk]*w[c];
                acc[1][c] += ax[1][kk]*w[c];
                acc[2][c] += ax[2][kk]*w[c];
                acc[3][c] += ax[3][kk]*w[c];
            }
        }
    }
}
static __device__ __forceinline__ void gemm_inner2(
    const float* __restrict__ sXr, const float* __restrict__ sW,
    float acc[2][8], int tx)
{
    #pragma unroll 2
    for (int k4 = 0; k4 < 128; k4 += 4){
        float ax[2][4];
        *(float4*)ax[0] = *(const float4*)(sXr + k4);
        *(float4*)ax[1] = *(const float4*)(sXr + 128 + k4);
        #pragma unroll
        for (int kk = 0; kk < 4; kk++){
            float w[8];
            *(float4*)&w[0] = *(const float4*)(sW + (k4+kk)*128 + tx*8);
            *(float4*)&w[4] = *(const float4*)(sW + (k4+kk)*128 + tx*8 + 4);
            #pragma unroll
            for (int c = 0; c < 8; c++){
                acc[0][c] += ax[0][kk]*w[c];
                acc[1][c] += ax[1][kk]*w[c];
            }
        }
    }
}

// y=0: x<64 -> A GEMM (64 rows); x in [64,80) -> W2 frag prep; else exit
// y=1: x<64 -> B GEMM (64 rows); else exit
// y=2: all 128 -> value MLP both layers, 32 rows/CTA (balanced with cfg0/1)
__global__ __launch_bounds__(256) void prep1k(
    const float* __restrict__ x,   const float* __restrict__ aw1,
    const float* __restrict__ ab1, const float* __restrict__ vw1,
    const float* __restrict__ vb1, const float* __restrict__ vw2,
    const float* __restrict__ vb2, const float* __restrict__ aw2)
{
    const int cfg = blockIdx.y;
    const int tid = threadIdx.x;
    extern __shared__ float ps[];

    if (cfg == 2){
        // ---- value MLP, 32 rows ----
        float* sX = ps;            // 32x128
        float* sW = ps + 4096;     // 128x128
        const int r0 = blockIdx.x * 32;
        for (int i = tid; i < 1024; i += 256)
            ((float4*)sX)[i] = ((const float4*)(x + (size_t)r0*128))[i];
        for (int i = tid; i < 4096; i += 256)
            ((float4*)sW)[i] = ((const float4*)vw1)[i];
        __syncthreads();

        const int ty = tid >> 4, tx = tid & 15;
        float acc[2][8];
        #pragma unroll
        for (int q = 0; q < 2; q++)
            #pragma unroll
            for (int c = 0; c < 8; c++) acc[q][c] = vb1[tx*8 + c];
        gemm_inner2(sX + ty*2*128, sW, acc, tx);
        __syncthreads();

        #pragma unroll
        for (int q = 0; q < 2; q++){
            float o[8];
            #pragma unroll
            for (int c = 0; c < 8; c++) o[c] = fmaxf(acc[q][c], 0.f);
            *(float4*)(sX + (ty*2+q)*128 + tx*8)     = *(float4*)&o[0];
            *(float4*)(sX + (ty*2+q)*128 + tx*8 + 4) = *(float4*)&o[4];
        }
        for (int i = tid; i < 4096; i += 256)
            ((float4*)sW)[i] = ((const float4*)vw2)[i];
        __syncthreads();

        float acc2[2][8];
        #pragma unroll
        for (int q = 0; q < 2; q++)
            #pragma unroll
            for (int c = 0; c < 8; c++) acc2[q][c] = vb2[tx*8 + c];
        gemm_inner2(sX + ty*2*128, sW, acc2, tx);

        #pragma unroll
        for (int q = 0; q < 2; q++){
            const int r = r0 + ty*2 + q;
            size_t addr = (size_t)(r & 31)*16384 + (size_t)(r >> 5)*128 + tx*8;
            *(float4*)(g_Vb + addr)     = *(float4*)&acc2[q][0];
            *(float4*)(g_Vb + addr + 4) = *(float4*)&acc2[q][4];
        }
        return;
    }

    if (cfg == 0 && blockIdx.x >= 64){
        if (blockIdx.x >= 80) return;
        const int idx = (blockIdx.x - 64)*256 + tid;   // 0..4095
        const int c = idx >> 5, kt = (idx >> 2) & 7, tg = idx & 3;
        const int k0 = kt*16 + 2*tg;
        uint2 o;
        o.x = pack_h2(aw2[(k0  )*128 + c], aw2[(k0+1)*128 + c]);
        o.y = pack_h2(aw2[(k0+8)*128 + c], aw2[(k0+9)*128 + c]);
        g_W2h[c*32 + kt*4 + tg] = o;
        return;
    }
    if (blockIdx.x >= 64) return;

    // ---- A / B GEMM, 64 rows ----
    float* sX = ps;            // 64x128
    float* sW = ps + 8192;     // 128x128
    const int r0 = blockIdx.x * 64;
    const float* Wsrc = (cfg == 0) ? aw1 : (aw1 + 16384);

    for (int i = tid; i < 2048; i += 256)
        ((float4*)sX)[i] = ((const float4*)(x + (size_t)r0*128))[i];
    for (int i = tid; i < 4096; i += 256)
        ((float4*)sW)[i] = ((const float4*)Wsrc)[i];
    __syncthreads();

    const int ty = tid >> 4, tx = tid & 15;
    float acc[4][8];
    #pragma unroll
    for (int q = 0; q < 4; q++)
        #pragma unroll
        for (int c = 0; c < 8; c++)
            acc[q][c] = (cfg == 1) ? ab1[tx*8 + c] : 0.f;

    gemm_inner4(sX + ty*4*128, sW, acc, tx);

    unsigned int* dst = (cfg == 0) ? g_Ah : g_Bh;
    #pragma unroll
    for (int q = 0; q < 4; q++){
        const int r = r0 + ty*4 + q;
        size_t rowb = (cfg == 0) ? ((size_t)r*64)
                    : ((size_t)(r & 31)*8192 + (size_t)(r >> 5)*64);
        const size_t base = rowb + (size_t)(tx >> 1)*8 + (tx & 1);
        dst[base + 0] = pack_h2(acc[q][0], acc[q][1]);
        dst[base + 2] = pack_h2(acc[q][2], acc[q][3]);
        dst[base + 4] = pack_h2(acc[q][4], acc[q][5]);
        dst[base + 6] = pack_h2(acc[q][6], acc[q][7]);
    }
}

// ------------------------- main kernel -------------------------
// grid (GI, 32, 2): z = c-half. 256 thr, 8 warps: jq=wid&3 (32 j), chw=wid>>2 (32 c).
// 2 i-tiles per pass, mma m16n8k16.f16, 2 CTAs/SM, double-buffered sP (1 sync/pass).
__global__ __launch_bounds__(256, 2) void mainkern(
    const float* __restrict__ b2, float* __restrict__ outp)
{
    extern __shared__ float sm[];
    uint32_t* sA  = (uint32_t*)(sm + F_SA);
    uint32_t* sB  = (uint32_t*)(sm + F_SB);
    uint32_t* sW  = (uint32_t*)(sm + F_SW);
    float*    sV  = sm + F_SV;
    float*    sP  = sm + F_SP;
    float*    sBV = sm + F_BV;
    const uint2* sA2 = (const uint2*)sA;      // stride 36
    const uint2* sB2 = (const uint2*)sB;
    const uint2* sW2 = (const uint2*)sW;

    const int tid  = threadIdx.x;
    const int b    = blockIdx.y;
    const int cz   = blockIdx.z;
    const int i0   = blockIdx.x * NI;
    const int wid  = tid >> 5, lane = tid & 31;
    const int g    = lane >> 2, tg = lane & 3;
    const int jq   = wid & 3,  chw = wid >> 2;
    const int j0w  = jq * 32;
    const int c0w  = chw * 32;

    // ---- stage smem ----
    for (int idx = tid; idx < 512; idx += 256){
        int t = idx >> 4, q = idx & 15;
        uint4 v = ((const uint4*)g_Ah)[(size_t)((i0 + t)*32 + b)*16 + q];
        *(uint4*)(sA + t*72 + q*4) = v;
    }
    for (int idx = tid; idx < 2048; idx += 256){
        int j = idx >> 4, q = idx & 15;
        uint4 v = ((const uint4*)g_Bh)[((size_t)b*128 + j)*16 + q];
        *(uint4*)(sB + j*72 + q*4) = v;
    }
    for (int idx = tid; idx < 1024; idx += 256){
        int c = idx >> 4, q = idx & 15;
        uint4 v = ((const uint4*)g_W2h)[(cz*64 + c)*16 + q];
        *(uint4*)(sW + c*72 + q*4) = v;
    }
    for (int idx = tid; idx < 2048; idx += 256){
        int j = idx >> 4, q = idx & 15;
        float4 v = ((const float4*)g_Vb)[((size_t)b*128 + j)*32 + cz*16 + q];
        *(float4*)(sV + j*72 + q*4) = v;
    }
    __syncthreads();

    if (tid < 64){
        float s = 0.f;
        #pragma unroll 8
        for (int j = 0; j < 128; j++) s += sV[j*72 + tid];
        sBV[tid] = b2[cz*64 + tid] * s;
    }
    __syncthreads();

    for (int t0 = 0; t0 < NI; t0 += 2){
        float* sPp = sP + ((t0 >> 1) & 1)*1024;

        float d[2][2][4][4];
        #pragma unroll
        for (int tt = 0; tt < 2; tt++)
            #pragma unroll
            for (int jt = 0; jt < 2; jt++)
                #pragma unroll
                for (int nt = 0; nt < 4; nt++)
                    #pragma unroll
                    for (int q = 0; q < 4; q++) d[tt][jt][nt][q] = 0.f;

        #pragma unroll
        for (int kt = 0; kt < 8; kt++){
            uint2 bu[2][2];
            #pragma unroll
            for (int jt = 0; jt < 2; jt++){
                const int j = j0w + jt*16 + g;
                bu[jt][0] = sB2[j*36     + kt*4 + tg];
                bu[jt][1] = sB2[(j+8)*36 + kt*4 + tg];
            }
            uint32_t fr[2][2][4];
            #pragma unroll
            for (int tt = 0; tt < 2; tt++){
                const uint2 au = sA2[(t0+tt)*36 + kt*4 + tg];
                #pragma unroll
                for (int jt = 0; jt < 2; jt++){
                    fr[tt][jt][0] = relu2add(au.x, bu[jt][0].x);
                    fr[tt][jt][1] = relu2add(au.x, bu[jt][1].x);
                    fr[tt][jt][2] = relu2add(au.y, bu[jt][0].y);
                    fr[tt][jt][3] = relu2add(au.y, bu[jt][1].y);
                }
            }
            #pragma unroll
            for (int nt = 0; nt < 4; nt++){
                const uint2 wf = sW2[(c0w + nt*8 + g)*36 + kt*4 + tg];
                #pragma unroll
                for (int tt = 0; tt < 2; tt++)
                    #pragma unroll
                    for (int jt = 0; jt < 2; jt++)
                        asm volatile(
                            "mma.sync.aligned.m16n8k16.row.col.f32.f16.f16.f32 "
                            "{%0,%1,%2,%3}, {%4,%5,%6,%7}, {%8,%9}, {%0,%1,%2,%3};"
                            : "+f"(d[tt][jt][nt][0]), "+f"(d[tt][jt][nt][1]),
                              "+f"(d[tt][jt][nt][2]), "+f"(d[tt][jt][nt][3])
                            : "r"(fr[tt][jt][0]), "r"(fr[tt][jt][1]),
                              "r"(fr[tt][jt][2]), "r"(fr[tt][jt][3]),
                              "r"(wf.x), "r"(wf.y));
            }
        }

        // ---- epilogue: value-weighted j-reduction ----
        #pragma unroll
        for (int tt = 0; tt < 2; tt++){
            #pragma unroll
            for (int nt = 0; nt < 4; nt++){
                const int c = c0w + nt*8 + 2*tg;
                float p0 = 0.f, p1 = 0.f;
                #pragma unroll
                for (int jt = 0; jt < 2; jt++){
                    const int j = j0w + jt*16 + g;
                    float2 v0 = *(const float2*)(sV + j*72 + c);
                    float2 v8 = *(const float2*)(sV + (j+8)*72 + c);
                    p0 += d[tt][jt][nt][0]*v0.x + d[tt][jt][nt][2]*v8.x;
                    p1 += d[tt][jt][nt][1]*v0.y + d[tt][jt][nt][3]*v8.y;
                }
                #pragma unroll
                for (int m = 4; m < 32; m <<= 1){
                    p0 += __shfl_xor_sync(0xffffffffu, p0, m);
                    p1 += __shfl_xor_sync(0xffffffffu, p1, m);
                }
                if (g == 0)
                    *(float2*)(sPp + tt*256 + jq*64 + c) = make_float2(p0, p1);
            }
        }
        __syncthreads();
        if (tid < 128){
            const int tt = tid >> 6, c = tid & 63;
            const float* p = sPp + tt*256;
            float r = p[c] + p[64+c] + p[128+c] + p[192+c] + sBV[c];
            outp[(size_t)(i0 + t0 + tt)*4096 + (size_t)b*128 + cz*64 + c] = r;
        }
        // no trailing sync: next pass writes the other sP buffer
    }
}

// ---------------------------------------------------------------------------
extern "C" void kernel_launch(void* const* d_in, const int* in_sizes, int n_in,
                              void* d_out, int out_size)
{
    const float* x   = (const float*)d_in[0];
    const float* aw1 = (const float*)d_in[1];
    const float* ab1 = (const float*)d_in[2];
    const float* aw2 = (const float*)d_in[3];
    const float* ab2 = (const float*)d_in[4];
    const float* vw1 = (const float*)d_in[5];
    const float* vb1 = (const float*)d_in[6];
    const float* vw2 = (const float*)d_in[7];
    const float* vb2 = (const float*)d_in[8];
    float* outp = (float*)d_out;

    cudaFuncSetAttribute(prep1k,   cudaFuncAttributeMaxDynamicSharedMemorySize, 98304);
    cudaFuncSetAttribute(mainkern, cudaFuncAttributeMaxDynamicSharedMemorySize, SMEM_MAIN);

    prep1k<<<dim3(128, 3), 256, 98304>>>(x, aw1, ab1, vw1, vb1, vw2, vb2, aw2);
    mainkern<<<dim3(GI, 32, 2), 256, SMEM_MAIN>>>(ab2, outp);
}

// round 15
// speedup vs baseline: 1.0208x; 1.0208x over previous
#include <cuda_runtime.h>
#include <cuda_fp16.h>
#include <cstdint>

#define NI 32            // i-tiles per CTA
#define GI 4             // grid.x (GI*NI = 128 = L)

// ---------------- device scratch (no allocs allowed) ----------------
// word order within a 64-word row: w = kt*8 + 2*tg + h  (kt=0..7, tg=0..3, h=0..1)
__device__ unsigned int g_Ah[4096*64];     // [r][64], r=i*32+b
__device__ unsigned int g_Bh[32*128*64];   // [b][j][64]
__device__ float        g_Vb[32*128*128];  // [b][j][c] fp32 value
__device__ uint2        g_W2h[128*32];     // [c][kt*4+tg] fp16 frag pairs

// ---------------- main smem layout (float units) ----------------
#define F_SA 0                 // 32 t * 72 words
#define F_SB 2304              // 128 j * 72 words
#define F_SW 11520             // 64 c * 72 words
#define F_SV 16128             // 128 j * 72 floats
#define F_SP 25344             // 2 bufs * (2 tt * 8 jq * 64) = 2048
#define F_BV 27392             // 64
#define SMEM_MAIN (27456*4)    // 109824 B -> 2 CTAs/SM

static __device__ __forceinline__ uint32_t pack_h2(float lo, float hi){
    uint32_t r;
    asm("cvt.rn.f16x2.f32 %0, %1, %2;" : "=r"(r) : "f"(hi), "f"(lo));
    return r;
}
static __device__ __forceinline__ uint32_t relu2add(uint32_t a, uint32_t b){
    uint32_t r;
    asm("{ .reg .b32 t; add.f16x2 t, %1, %2; max.f16x2 %0, t, %3; }"
        : "=r"(r) : "r"(a), "r"(b), "r"(0u));
    return r;
}

// ------------------------- prep GEMM inner (float4 X loads) -------------
static __device__ __forceinline__ void gemm_inner(
    const float* __restrict__ sXr, const float* __restrict__ sW,
    float acc[4][8], int tx)
{
    #pragma unroll 2
    for (int k4 = 0; k4 < 128; k4 += 4){
        float ax[4][4];
        #pragma unroll
        for (int q = 0; q < 4; q++)
            *(float4*)ax[q] = *(const float4*)(sXr + q*128 + k4);
        #pragma unroll
        for (int kk = 0; kk < 4; kk++){
            float w[8];
            *(float4*)&w[0] = *(const float4*)(sW + (k4+kk)*128 + tx*8);
            *(float4*)&w[4] = *(const float4*)(sW + (k4+kk)*128 + tx*8 + 4);
            #pragma unroll
            for (int c = 0; c < 8; c++){
                acc[0][c] += ax[0][kk]*w[c];
                acc[1][c] += ax[1][kk]*w[c];
                acc[2][c] += ax[2][kk]*w[c];
                acc[3][c] += ax[3][kk]*w[c];
            }
        }
    }
}

// cfg0: A=x@W1_top -> g_Ah ; cfg1: B=x@W1_bot+b1 -> g_Bh ;
// cfg2: V=relu(x@Vw1+vb1)@Vw2+vb2 -> g_Vb ; cfg3: W2 -> g_W2h
__global__ __launch_bounds__(256) void prep1k(
    const float* __restrict__ x,   const float* __restrict__ aw1,
    const float* __restrict__ ab1, const float* __restrict__ vw1,
    const float* __restrict__ vb1, const float* __restrict__ vw2,
    const float* __restrict__ vb2, const float* __restrict__ aw2)
{
    const int cfg = blockIdx.y;
    const int tid = threadIdx.x;

    if (cfg == 3){
        if (blockIdx.x >= 16) return;
        const int idx = blockIdx.x*256 + tid;      // 0..4095
        const int c = idx >> 5, kt = (idx >> 2) & 7, tg = idx & 3;
        const int k0 = kt*16 + 2*tg;
        uint2 o;
        o.x = pack_h2(aw2[(k0  )*128 + c], aw2[(k0+1)*128 + c]);
        o.y = pack_h2(aw2[(k0+8)*128 + c], aw2[(k0+9)*128 + c]);
        g_W2h[c*32 + kt*4 + tg] = o;
        return;
    }

    extern __shared__ float ps[];
    float* sX = ps;            // 64x128
    float* sW = ps + 8192;     // 128x128
    const int r0 = blockIdx.x * 64;

    const float* Wsrc = (cfg == 0) ? aw1 : (cfg == 1) ? (aw1 + 16384) : vw1;
    for (int i = tid; i < 2048; i += 256)
        ((float4*)sX)[i] = ((const float4*)(x + (size_t)r0*128))[i];
    for (int i = tid; i < 4096; i += 256)
        ((float4*)sW)[i] = ((const float4*)Wsrc)[i];
    __syncthreads();

    const int ty = tid >> 4, tx = tid & 15;
    const float* bias = (cfg == 0) ? nullptr : (cfg == 1) ? ab1 : vb1;

    float acc[4][8];
    #pragma unroll
    for (int q = 0; q < 4; q++)
        #pragma unroll
        for (int c = 0; c < 8; c++)
            acc[q][c] = bias ? bias[tx*8 + c] : 0.f;

    gemm_inner(sX + ty*4*128, sW, acc, tx);

    if (cfg == 0 || cfg == 1){
        unsigned int* dst = (cfg == 0) ? g_Ah : g_Bh;
        #pragma unroll
        for (int q = 0; q < 4; q++){
            const int r = r0 + ty*4 + q;
            size_t rowb = (cfg == 0) ? ((size_t)r*64)
                        : ((size_t)(r & 31)*8192 + (size_t)(r >> 5)*64);
            const size_t base = rowb + (size_t)(tx >> 1)*8 + (tx & 1);
            dst[base + 0] = pack_h2(acc[q][0], acc[q][1]);
            dst[base + 2] = pack_h2(acc[q][2], acc[q][3]);
            dst[base + 4] = pack_h2(acc[q][4], acc[q][5]);
            dst[base + 6] = pack_h2(acc[q][6], acc[q][7]);
        }
        return;
    }

    // cfg2: relu(layer1) back to sX, stage Vw2, layer2
    __syncthreads();
    #pragma unroll
    for (int q = 0; q < 4; q++){
        float o[8];
        #pragma unroll
        for (int c = 0; c < 8; c++) o[c] = fmaxf(acc[q][c], 0.f);
        *(float4*)(sX + (ty*4+q)*128 + tx*8)     = *(float4*)&o[0];
        *(float4*)(sX + (ty*4+q)*128 + tx*8 + 4) = *(float4*)&o[4];
    }
    for (int i = tid; i < 4096; i += 256)
        ((float4*)sW)[i] = ((const float4*)vw2)[i];
    __syncthreads();

    float acc2[4][8];
    #pragma unroll
    for (int q = 0; q < 4; q++)
        #pragma unroll
        for (int c = 0; c < 8; c++) acc2[q][c] = vb2[tx*8 + c];
    gemm_inner(sX + ty*4*128, sW, acc2, tx);

    #pragma unroll
    for (int q = 0; q < 4; q++){
        const int r = r0 + ty*4 + q;
        size_t addr = (size_t)(r & 31)*16384 + (size_t)(r >> 5)*128 + tx*8;
        *(float4*)(g_Vb + addr)     = *(float4*)&acc2[q][0];
        *(float4*)(g_Vb + addr + 4) = *(float4*)&acc2[q][4];
    }
}

// ------------------------- main kernel -------------------------
// grid (GI, 32, 2): z = c-half. 256 thr, 8 warps: jq = wid -> 16 j-rows each,
// every warp spans the full 64-c half (nt 0..7). H computed once per CTA.
// 2 i-tiles per pass, mma m16n8k16.f16, 2 CTAs/SM, double-buffered sP.
__global__ __launch_bounds__(256, 2) void mainkern(
    const float* __restrict__ b2, float* __restrict__ outp)
{
    extern __shared__ float sm[];
    uint32_t* sA  = (uint32_t*)(sm + F_SA);
    uint32_t* sB  = (uint32_t*)(sm + F_SB);
    uint32_t* sW  = (uint32_t*)(sm + F_SW);
    float*    sV  = sm + F_SV;
    float*    sP  = sm + F_SP;
    float*    sBV = sm + F_BV;
    const uint2* sA2 = (const uint2*)sA;      // stride 36
    const uint2* sB2 = (const uint2*)sB;
    const uint2* sW2 = (const uint2*)sW;

    const int tid  = threadIdx.x;
    const int b    = blockIdx.y;
    const int cz   = blockIdx.z;
    const int i0   = blockIdx.x * NI;
    const int wid  = tid >> 5, lane = tid & 31;
    const int g    = lane >> 2, tg = lane & 3;
    const int j0w  = wid * 16;                // 16 j-rows per warp

    // ---- stage smem ----
    for (int idx = tid; idx < 512; idx += 256){
        int t = idx >> 4, q = idx & 15;
        uint4 v = ((const uint4*)g_Ah)[(size_t)((i0 + t)*32 + b)*16 + q];
        *(uint4*)(sA + t*72 + q*4) = v;
    }
    for (int idx = tid; idx < 2048; idx += 256){
        int j = idx >> 4, q = idx & 15;
        uint4 v = ((const uint4*)g_Bh)[((size_t)b*128 + j)*16 + q];
        *(uint4*)(sB + j*72 + q*4) = v;
    }
    for (int idx = tid; idx < 1024; idx += 256){
        int c = idx >> 4, q = idx & 15;
        uint4 v = ((const uint4*)g_W2h)[(cz*64 + c)*16 + q];
        *(uint4*)(sW + c*72 + q*4) = v;
    }
    for (int idx = tid; idx < 2048; idx += 256){
        int j = idx >> 4, q = idx & 15;
        float4 v = ((const float4*)g_Vb)[((size_t)b*128 + j)*32 + cz*16 + q];
        *(float4*)(sV + j*72 + q*4) = v;
    }
    __syncthreads();

    if (tid < 64){
        float s = 0.f;
        #pragma unroll 8
        for (int j = 0; j < 128; j++) s += sV[j*72 + tid];
        sBV[tid] = b2[cz*64 + tid] * s;
    }
    __syncthreads();

    for (int t0 = 0; t0 < NI; t0 += 2){
        float* sPp = sP + ((t0 >> 1) & 1)*1024;

        float d[2][8][4];
        #pragma unroll
        for (int tt = 0; tt < 2; tt++)
            #pragma unroll
            for (int nt = 0; nt < 8; nt++)
                #pragma unroll
                for (int q = 0; q < 4; q++) d[tt][nt][q] = 0.f;

        #pragma unroll
        for (int kt = 0; kt < 8; kt++){
            const uint2 bu0 = sB2[(j0w + g)*36     + kt*4 + tg];
            const uint2 bu1 = sB2[(j0w + 8 + g)*36 + kt*4 + tg];
            uint32_t fr[2][4];
            #pragma unroll
            for (int tt = 0; tt < 2; tt++){
                const uint2 au = sA2[(t0+tt)*36 + kt*4 + tg];
                fr[tt][0] = relu2add(au.x, bu0.x);
                fr[tt][1] = relu2add(au.x, bu1.x);
                fr[tt][2] = relu2add(au.y, bu0.y);
                fr[tt][3] = relu2add(au.y, bu1.y);
            }
            #pragma unroll
            for (int nt = 0; nt < 8; nt++){
                const uint2 wf = sW2[(nt*8 + g)*36 + kt*4 + tg];
                #pragma unroll
                for (int tt = 0; tt < 2; tt++)
                    asm volatile(
                        "mma.sync.aligned.m16n8k16.row.col.f32.f16.f16.f32 "
                        "{%0,%1,%2,%3}, {%4,%5,%6,%7}, {%8,%9}, {%0,%1,%2,%3};"
                        : "+f"(d[tt][nt][0]), "+f"(d[tt][nt][1]),
                          "+f"(d[tt][nt][2]), "+f"(d[tt][nt][3])
                        : "r"(fr[tt][0]), "r"(fr[tt][1]),
                          "r"(fr[tt][2]), "r"(fr[tt][3]),
                          "r"(wf.x), "r"(wf.y));
            }
        }

        // ---- epilogue: value-weighted j-reduction (16 rows per warp) ----
        #pragma unroll
        for (int tt = 0; tt < 2; tt++){
            #pragma unroll
            for (int nt = 0; nt < 8; nt++){
                const int c = nt*8 + 2*tg;
                float2 v0 = *(const float2*)(sV + (j0w + g)*72 + c);
                float2 v8 = *(const float2*)(sV + (j0w + 8 + g)*72 + c);
                float p0 = d[tt][nt][0]*v0.x + d[tt][nt][2]*v8.x;
                float p1 = d[tt][nt][1]*v0.y + d[tt][nt][3]*v8.y;
                #pragma unroll
                for (int m = 4; m < 32; m <<= 1){
                    p0 += __shfl_xor_sync(0xffffffffu, p0, m);
                    p1 += __shfl_xor_sync(0xffffffffu, p1, m);
                }
                if (g == 0)
                    *(float2*)(sPp + tt*512 + wid*64 + c) = make_float2(p0, p1);
            }
        }
        __syncthreads();
        if (tid < 128){
            const int tt = tid >> 6, c = tid & 63;
            const float* p = sPp + tt*512;
            float r = sBV[c];
            #pragma unroll
            for (int q = 0; q < 8; q++) r += p[q*64 + c];
            outp[(size_t)(i0 + t0 + tt)*4096 + (size_t)b*128 + cz*64 + c] = r;
        }
        // no trailing sync: next pass writes the other sP buffer
    }
}

// ---------------------------------------------------------------------------
extern "C" void kernel_launch(void* const* d_in, const int* in_sizes, int n_in,
                              void* d_out, int out_size)
{
    const float* x   = (const float*)d_in[0];
    const float* aw1 = (const float*)d_in[1];
    const float* ab1 = (const float*)d_in[2];
    const float* aw2 = (const float*)d_in[3];
    const float* ab2 = (const float*)d_in[4];
    const float* vw1 = (const float*)d_in[5];
    const float* vb1 = (const float*)d_in[6];
    const float* vw2 = (const float*)d_in[7];
    const float* vb2 = (const float*)d_in[8];
    float* outp = (float*)d_out;

    cudaFuncSetAttribute(prep1k,   cudaFuncAttributeMaxDynamicSharedMemorySize, 98304);
    cudaFuncSetAttribute(mainkern, cudaFuncAttributeMaxDynamicSharedMemorySize, SMEM_MAIN);

    prep1k<<<dim3(64, 4), 256, 98304>>>(x, aw1, ab1, vw1, vb1, vw2, vb2, aw2);
    mainkern<<<dim3(GI, 32, 2), 256, SMEM_MAIN>>>(ab2, outp);
}

// round 17
// speedup vs baseline: 1.0862x; 1.0640x over previous
#include <cuda_runtime.h>
#include <cuda_fp16.h>
#include <cstdint>

#define NI 32            // i-tiles per CTA
#define GI 4             // grid.x (GI*NI = 128 = L)

// ---------------- device scratch (no allocs allowed) ----------------
// interleaved fp16-pair layout, 64 words/row: word w = kt*8 + 2*tg + h
// holds k = kt*16 + h*8 + 2*tg (and k+1)
__device__ unsigned int g_Ah[4096*64];     // [r][64], r=i*32+b
__device__ unsigned int g_Bh[32*128*64];   // [b][j][64]
__device__ unsigned int g_Hh[4096*64];     // value hidden, fp16
__device__ float        g_Vb[32*128*128];  // [b][j][c] fp32 value
__device__ uint2        g_W2h[128*32];     // [c][kt*4+tg] fp16 frag pairs

// ---------------- main smem layout (float units) ----------------
#define F_SA 0                 // 32 t * 72 words
#define F_SB 2304              // 128 j * 72 words
#define F_SW 11520             // 64 c * 72 words
#define F_SV 16128             // 128 j * 72 floats
#define F_SP 25344             // 2 bufs * 1024
#define F_BV 27392             // 64
#define SMEM_MAIN (27456*4)    // 109824 B -> 2 CTAs/SM

#define PREP_SMEM (2*128*72*4) // sX + sW, 73728 B

static __device__ __forceinline__ uint32_t pack_h2(float lo, float hi){
    uint32_t r;
    asm("cvt.rn.f16x2.f32 %0, %1, %2;" : "=r"(r) : "f"(hi), "f"(lo));
    return r;
}
static __device__ __forceinline__ uint32_t relu2add(uint32_t a, uint32_t b){
    uint32_t r;
    asm("{ .reg .b32 t; add.f16x2 t, %1, %2; max.f16x2 %0, t, %3; }"
        : "=r"(r) : "r"(a), "r"(b), "r"(0u));
    return r;
}
#define MMA16816(d, a0, a1, a2, a3, b0, b1) \
    asm volatile( \
        "mma.sync.aligned.m16n8k16.row.col.f32.f16.f16.f32 " \
        "{%0,%1,%2,%3}, {%4,%5,%6,%7}, {%8,%9}, {%0,%1,%2,%3};" \
        : "+f"((d)[0]), "+f"((d)[1]), "+f"((d)[2]), "+f"((d)[3]) \
        : "r"(a0), "r"(a1), "r"(a2), "r"(a3), "r"(b0), "r"(b1))

// ------------------------- prepmma1 -------------------------
// grid (32, 3), 256 thr. cfg0: A = x@W1_top (no bias) -> g_Ah
//                        cfg1: B = x@W1_bot + b1      -> g_Bh (b-major)
//                        cfg2: Vh = relu(x@Vw1 + vb1) -> g_Hh
// Each CTA: 128 rows. Stages x and its weight, converting fp32->fp16 frags.
__global__ __launch_bounds__(256) void prepmma1(
    const float* __restrict__ x,   const float* __restrict__ aw1,
    const float* __restrict__ ab1, const float* __restrict__ vw1,
    const float* __restrict__ vb1, const float* __restrict__ aw2)
{
    extern __shared__ uint32_t us[];
    uint32_t* sX = us;            // [row][72 words]
    uint32_t* sW = us + 128*72;   // [n][72 words]
    const int cfg = blockIdx.y;
    const int tid = threadIdx.x;
    const int r0  = blockIdx.x * 128;

    const float* Wsrc = (cfg == 0) ? aw1 : (cfg == 1) ? (aw1 + 16384) : vw1;
    const float* bias = (cfg == 0) ? nullptr : (cfg == 1) ? ab1 : vb1;

    // stage X (fp32 -> fp16 interleaved)
    for (int i = tid; i < 4096; i += 256){
        const int rr = i >> 5, p = i & 31;
        const int k0 = (p >> 2)*16 + 2*(p & 3);
        const float* xr = x + (size_t)(r0 + rr)*128;
        uint2 o;
        o.x = pack_h2(xr[k0],     xr[k0+1]);
        o.y = pack_h2(xr[k0+8],   xr[k0+9]);
        *(uint2*)&sX[rr*72 + p*2] = o;
    }
    // stage W (fp32 -> frag layout)
    for (int i = tid; i < 4096; i += 256){
        const int n = i >> 5, p = i & 31;
        const int k0 = (p >> 2)*16 + 2*(p & 3);
        uint2 o;
        o.x = pack_h2(Wsrc[(k0  )*128 + n], Wsrc[(k0+1)*128 + n]);
        o.y = pack_h2(Wsrc[(k0+8)*128 + n], Wsrc[(k0+9)*128 + n]);
        *(uint2*)&sW[n*72 + p*2] = o;
    }
    // piggyback: W2 fragments (cfg0 CTAs, 128 entries each)
    if (cfg == 0 && tid < 128){
        const int idx = blockIdx.x*128 + tid;      // 0..4095
        const int c = idx >> 5, p = idx & 31;
        const int kt = p >> 2, tg2 = p & 3;
        const int k0 = kt*16 + 2*tg2;
        uint2 o;
        o.x = pack_h2(aw2[(k0  )*128 + c], aw2[(k0+1)*128 + c]);
        o.y = pack_h2(aw2[(k0+8)*128 + c], aw2[(k0+9)*128 + c]);
        g_W2h[c*32 + kt*4 + tg2] = o;
    }
    __syncthreads();

    const int wid = tid >> 5, lane = tid & 31;
    const int g = lane >> 2, tg = lane & 3;
    const int rw = wid * 16;
    const uint2* sX2 = (const uint2*)sX;   // stride 36
    const uint2* sW2 = (const uint2*)sW;

    float d[16][4];
    #pragma unroll
    for (int nt = 0; nt < 16; nt++){
        const int c = nt*8 + 2*tg;
        const float b0 = bias ? bias[c] : 0.f;
        const float b1 = bias ? bias[c+1] : 0.f;
        d[nt][0] = b0; d[nt][1] = b1; d[nt][2] = b0; d[nt][3] = b1;
    }

    #pragma unroll
    for (int kt = 0; kt < 8; kt++){
        const uint2 au0 = sX2[(rw + g)*36     + kt*4 + tg];
        const uint2 au1 = sX2[(rw + 8 + g)*36 + kt*4 + tg];
        #pragma unroll
        for (int nt = 0; nt < 16; nt++){
            const uint2 wf = sW2[(nt*8 + g)*36 + kt*4 + tg];
            MMA16816(d[nt], au0.x, au1.x, au0.y, au1.y, wf.x, wf.y);
        }
    }

    // epilogue: pack to fp16 interleaved global layouts
    #pragma unroll
    for (int nt = 0; nt < 16; nt++){
        float d0 = d[nt][0], d1 = d[nt][1], d2 = d[nt][2], d3 = d[nt][3];
        if (cfg == 2){
            d0 = fmaxf(d0, 0.f); d1 = fmaxf(d1, 0.f);
            d2 = fmaxf(d2, 0.f); d3 = fmaxf(d3, 0.f);
        }
        const uint32_t u0 = pack_h2(d0, d1);
        const uint32_t u1 = pack_h2(d2, d3);
        const int w = (nt >> 1)*8 + 2*tg + (nt & 1);
        const int rA = r0 + rw + g, rB = rA + 8;
        if (cfg == 0){
            g_Ah[(size_t)rA*64 + w] = u0;
            g_Ah[(size_t)rB*64 + w] = u1;
        } else if (cfg == 1){
            g_Bh[(size_t)(rA & 31)*8192 + (size_t)(rA >> 5)*64 + w] = u0;
            g_Bh[(size_t)(rB & 31)*8192 + (size_t)(rB >> 5)*64 + w] = u1;
        } else {
            g_Hh[(size_t)rA*64 + w] = u0;
            g_Hh[(size_t)rB*64 + w] = u1;
        }
    }
}

// ------------------------- prepmma2: V = Vh @ Vw2 + vb2 (fp32 out) ------
__global__ __launch_bounds__(256) void prepmma2(
    const float* __restrict__ vw2, const float* __restrict__ vb2)
{
    extern __shared__ uint32_t us[];
    uint32_t* sX = us;
    uint32_t* sW = us + 128*72;
    const int tid = threadIdx.x;
    const int r0  = blockIdx.x * 128;

    for (int i = tid; i < 2048; i += 256){
        const int rr = i >> 4, q = i & 15;
        uint4 v = ((const uint4*)g_Hh)[(size_t)(r0 + rr)*16 + q];
        *(uint4*)&sX[rr*72 + q*4] = v;
    }
    for (int i = tid; i < 4096; i += 256){
        const int n = i >> 5, p = i & 31;
        const int k0 = (p >> 2)*16 + 2*(p & 3);
        uint2 o;
        o.x = pack_h2(vw2[(k0  )*128 + n], vw2[(k0+1)*128 + n]);
        o.y = pack_h2(vw2[(k0+8)*128 + n], vw2[(k0+9)*128 + n]);
        *(uint2*)&sW[n*72 + p*2] = o;
    }
    __syncthreads();

    const int wid = tid >> 5, lane = tid & 31;
    const int g = lane >> 2, tg = lane & 3;
    const int rw = wid * 16;
    const uint2* sX2 = (const uint2*)sX;
    const uint2* sW2 = (const uint2*)sW;

    float d[16][4];
    #pragma unroll
    for (int nt = 0; nt < 16; nt++){
        const int c = nt*8 + 2*tg;
        d[nt][0] = vb2[c]; d[nt][1] = vb2[c+1];
        d[nt][2] = vb2[c]; d[nt][3] = vb2[c+1];
    }
    #pragma unroll
    for (int kt = 0; kt < 8; kt++){
        const uint2 au0 = sX2[(rw + g)*36     + kt*4 + tg];
        const uint2 au1 = sX2[(rw + 8 + g)*36 + kt*4 + tg];
        #pragma unroll
        for (int nt = 0; nt < 16; nt++){
            const uint2 wf = sW2[(nt*8 + g)*36 + kt*4 + tg];
            MMA16816(d[nt], au0.x, au1.x, au0.y, au1.y, wf.x, wf.y);
        }
    }
    #pragma unroll
    for (int nt = 0; nt < 16; nt++){
        const int c = nt*8 + 2*tg;
        const int rA = r0 + rw + g, rB = rA + 8;
        const size_t oA = (size_t)(rA & 31)*16384 + (size_t)(rA >> 5)*128 + c;
        const size_t oB = (size_t)(rB & 31)*16384 + (size_t)(rB >> 5)*128 + c;
        *(float2*)&g_Vb[oA] = make_float2(d[nt][0], d[nt][1]);
        *(float2*)&g_Vb[oB] = make_float2(d[nt][2], d[nt][3]);
    }
}

// ------------------------- main kernel (unchanged from R15) -------------
__global__ __launch_bounds__(256, 2) void mainkern(
    const float* __restrict__ b2, float* __restrict__ outp)
{
    extern __shared__ float sm[];
    uint32_t* sA  = (uint32_t*)(sm + F_SA);
    uint32_t* sB  = (uint32_t*)(sm + F_SB);
    uint32_t* sW  = (uint32_t*)(sm + F_SW);
    float*    sV  = sm + F_SV;
    float*    sP  = sm + F_SP;
    float*    sBV = sm + F_BV;
    const uint2* sA2 = (const uint2*)sA;
    const uint2* sB2 = (const uint2*)sB;
    const uint2* sW2 = (const uint2*)sW;

    const int tid  = threadIdx.x;
    const int b    = blockIdx.y;
    const int cz   = blockIdx.z;
    const int i0   = blockIdx.x * NI;
    const int wid  = tid >> 5, lane = tid & 31;
    const int g    = lane >> 2, tg = lane & 3;
    const int j0w  = wid * 16;

    for (int idx = tid; idx < 512; idx += 256){
        int t = idx >> 4, q = idx & 15;
        uint4 v = ((const uint4*)g_Ah)[(size_t)((i0 + t)*32 + b)*16 + q];
        *(uint4*)(sA + t*72 + q*4) = v;
    }
    for (int idx = tid; idx < 2048; idx += 256){
        int j = idx >> 4, q = idx & 15;
        uint4 v = ((const uint4*)g_Bh)[((size_t)b*128 + j)*16 + q];
        *(uint4*)(sB + j*72 + q*4) = v;
    }
    for (int idx = tid; idx < 1024; idx += 256){
        int c = idx >> 4, q = idx & 15;
        uint4 v = ((const uint4*)g_W2h)[(cz*64 + c)*16 + q];
        *(uint4*)(sW + c*72 + q*4) = v;
    }
    for (int idx = tid; idx < 2048; idx += 256){
        int j = idx >> 4, q = idx & 15;
        float4 v = ((const float4*)g_Vb)[((size_t)b*128 + j)*32 + cz*16 + q];
        *(float4*)(sV + j*72 + q*4) = v;
    }
    __syncthreads();

    if (tid < 64){
        float s = 0.f;
        #pragma unroll 8
        for (int j = 0; j < 128; j++) s += sV[j*72 + tid];
        sBV[tid] = b2[cz*64 + tid] * s;
    }
    __syncthreads();

    for (int t0 = 0; t0 < NI; t0 += 2){
        float* sPp = sP + ((t0 >> 1) & 1)*1024;

        float d[2][8][4];
        #pragma unroll
        for (int tt = 0; tt < 2; tt++)
            #pragma unroll
            for (int nt = 0; nt < 8; nt++)
                #pragma unroll
                for (int q = 0; q < 4; q++) d[tt][nt][q] = 0.f;

        #pragma unroll
        for (int kt = 0; kt < 8; kt++){
            const uint2 bu0 = sB2[(j0w + g)*36     + kt*4 + tg];
            const uint2 bu1 = sB2[(j0w + 8 + g)*36 + kt*4 + tg];
            uint32_t fr[2][4];
            #pragma unroll
            for (int tt = 0; tt < 2; tt++){
                const uint2 au = sA2[(t0+tt)*36 + kt*4 + tg];
                fr[tt][0] = relu2add(au.x, bu0.x);
                fr[tt][1] = relu2add(au.x, bu1.x);
                fr[tt][2] = relu2add(au.y, bu0.y);
                fr[tt][3] = relu2add(au.y, bu1.y);
            }
            #pragma unroll
            for (int nt = 0; nt < 8; nt++){
                const uint2 wf = sW2[(nt*8 + g)*36 + kt*4 + tg];
                #pragma unroll
                for (int tt = 0; tt < 2; tt++)
                    MMA16816(d[tt][nt], fr[tt][0], fr[tt][1],
                             fr[tt][2], fr[tt][3], wf.x, wf.y);
            }
        }

        #pragma unroll
        for (int tt = 0; tt < 2; tt++){
            #pragma unroll
            for (int nt = 0; nt < 8; nt++){
                const int c = nt*8 + 2*tg;
                float2 v0 = *(const float2*)(sV + (j0w + g)*72 + c);
                float2 v8 = *(const float2*)(sV + (j0w + 8 + g)*72 + c);
                float p0 = d[tt][nt][0]*v0.x + d[tt][nt][2]*v8.x;
                float p1 = d[tt][nt][1]*v0.y + d[tt][nt][3]*v8.y;
                #pragma unroll
                for (int m = 4; m < 32; m <<= 1){
                    p0 += __shfl_xor_sync(0xffffffffu, p0, m);
                    p1 += __shfl_xor_sync(0xffffffffu, p1, m);
                }
                if (g == 0)
                    *(float2*)(sPp + tt*512 + wid*64 + c) = make_float2(p0, p1);
            }
        }
        __syncthreads();
        if (tid < 128){
            const int tt = tid >> 6, c = tid & 63;
            const float* p = sPp + tt*512;
            float r = sBV[c];
            #pragma unroll
            for (int q = 0; q < 8; q++) r += p[q*64 + c];
            outp[(size_t)(i0 + t0 + tt)*4096 + (size_t)b*128 + cz*64 + c] = r;
        }
    }
}

// ---------------------------------------------------------------------------
extern "C" void kernel_launch(void* const* d_in, const int* in_sizes, int n_in,
                              void* d_out, int out_size)
{
    const float* x   = (const float*)d_in[0];
    const float* aw1 = (const float*)d_in[1];
    const float* ab1 = (const float*)d_in[2];
    const float* aw2 = (const float*)d_in[3];
    const float* ab2 = (const float*)d_in[4];
    const float* vw1 = (const float*)d_in[5];
    const float* vb1 = (const float*)d_in[6];
    const float* vw2 = (const float*)d_in[7];
    const float* vb2 = (const float*)d_in[8];
    float* outp = (float*)d_out;

    cudaFuncSetAttribute(prepmma1, cudaFuncAttributeMaxDynamicSharedMemorySize, PREP_SMEM);
    cudaFuncSetAttribute(prepmma2, cudaFuncAttributeMaxDynamicSharedMemorySize, PREP_SMEM);
    cudaFuncSetAttribute(mainkern, cudaFuncAttributeMaxDynamicSharedMemorySize, SMEM_MAIN);

    prepmma1<<<dim3(32, 3), 256, PREP_SMEM>>>(x, aw1, ab1, vw1, vb1, aw2);
    prepmma2<<<32, 256, PREP_SMEM>>>(vw2, vb2);
    mainkern<<<dim3(GI, 32, 2), 256, SMEM_MAIN>>>(ab2, outp);
}